// round 4
// baseline (speedup 1.0000x reference)
#include <cuda_runtime.h>
#include <cstdint>

// LSTM T=1024, B=64, D=512 — two kernels in one graph.
// lstm_zx : Zx[t] = x_t @ Wi + b (parallel over t), CTA-local layout.
// lstm_rec: z = Zx[t] + h @ Wh; gates; h update. Cross-CTA sync via
//           per-CTA epoch flags (no contended atomics).

#define TS   1024
#define BB   64
#define DD   512
#define NCTA 128
#define NTHR 512

#define BUF_STRIDE 516
#define BUF_FLOATS (32 * BUF_STRIDE)
#define WS_FLOATS  (16 * 512)
#define RED_STRIDE 17
#define RED_FLOATS (8 * 64 * RED_STRIDE)

__device__ float g_zx[(size_t)TS * NCTA * 1024];  // [t][cta][b][dloc][gate]
__device__ float g_hbuf[2][BB * DD];
__device__ unsigned g_count = 0;
__device__ volatile unsigned g_gen = 0;
__device__ unsigned g_flags[NCTA * 8];            // padded: 1 flag / 32 B

__device__ __forceinline__ void fma2(unsigned long long& d,
                                     unsigned long long a,
                                     unsigned long long b) {
    asm volatile("fma.rn.f32x2 %0, %1, %2, %0;" : "+l"(d) : "l"(a), "l"(b));
}
__device__ __forceinline__ float sigf(float x) {
    return __fdividef(1.0f, 1.0f + __expf(-x));
}
__device__ __forceinline__ float tanhfast(float x) {
    float e = __expf(-2.0f * x);
    return __fdividef(1.0f - e, 1.0f + e);
}
__device__ __forceinline__ unsigned ldflag(const unsigned* p) {
    unsigned v;
    asm volatile("ld.global.cg.u32 %0, [%1];" : "=r"(v) : "l"(p));
    return v;
}

__device__ __forceinline__ void cpa16(float* dst, const float* src) {
    unsigned s = (unsigned)__cvta_generic_to_shared(dst);
    asm volatile("cp.async.cg.shared.global [%0], [%1], 16;" :: "r"(s), "l"(src));
}
#define CPA_COMMIT() asm volatile("cp.async.commit_group;" ::: "memory")
#define CPA_WAIT1()  asm volatile("cp.async.wait_group 1;" ::: "memory")
#define CPA_WAIT0()  asm volatile("cp.async.wait_group 0;" ::: "memory")

__device__ __forceinline__ void pf_tile(float* dst, const float* gsrc) {
    int r  = threadIdx.x >> 4;
    int c0 = threadIdx.x & 15;
    const float* s = gsrc + r * 512;
    float* d = dst + r * BUF_STRIDE;
#pragma unroll
    for (int j = 0; j < 8; ++j) {
        int c = c0 + j * 16;
        cpa16(d + c * 4, s + c * 4);
    }
}

__device__ __forceinline__ void fill_ws(float* Ws, const float* W, int d0) {
    for (int i = threadIdx.x; i < 16 * 512; i += NTHR) {
        int c = i >> 9, k = i & 511;
        int zc = ((c >> 2) << 9) + d0 + (c & 3);
        float w = W[(size_t)k * 2048 + zc];
        int kq = k >> 2;
        int u  = (kq & ~7) | ((kq ^ (c >> 1)) & 7);
        Ws[(c << 7 | u) * 4 + (k & 3)] = w;
    }
}

__device__ __forceinline__ void gemm_tile(const float* __restrict__ Ws,
                                          const float* __restrict__ buf,
                                          unsigned long long* acc,
                                          int cp, int bhq, int chunk) {
    const ulonglong2* wp0 = (const ulonglong2*)Ws + (2 * cp) * 128 + chunk * 16;
    const ulonglong2* wp1 = wp0 + 128;
    const ulonglong2* ap  = (const ulonglong2*)buf + bhq * 129 + chunk * 16;
#pragma unroll 4
    for (int kk = 0; kk < 16; ++kk) {
        int u = (kk & 8) | ((kk ^ cp) & 7);
        ulonglong2 w0 = wp0[u];
        ulonglong2 w1 = wp1[u];
#pragma unroll
        for (int bi = 0; bi < 4; ++bi) {
            ulonglong2 a = ap[bi * 1032 + kk];
            fma2(acc[bi],     w0.x, a.x);
            fma2(acc[bi],     w0.y, a.y);
            fma2(acc[4 + bi], w1.x, a.x);
            fma2(acc[4 + bi], w1.y, a.y);
        }
    }
}

__device__ __forceinline__ void write_partials(float* red,
                                               unsigned long long* accA,
                                               unsigned long long* accB,
                                               int cp, int bhq, int chunk) {
#pragma unroll
    for (int h = 0; h < 2; ++h) {
        unsigned long long* ac = h ? accB : accA;
#pragma unroll
        for (int ci = 0; ci < 2; ++ci)
#pragma unroll
            for (int bi = 0; bi < 4; ++bi) {
                float2 p = *(float2*)&ac[ci * 4 + bi];
                int b = h * 32 + bhq + bi * 8;
                red[(chunk * 64 + b) * RED_STRIDE + 2 * cp + ci] = p.x + p.y;
            }
    }
}

// ========================= PHASE 1 KERNEL =========================
extern "C" __global__ void __launch_bounds__(NTHR, 1)
lstm_zx(const float* __restrict__ x,
        const float* __restrict__ Wi,
        const float* __restrict__ bias) {
    extern __shared__ float smem[];
    float* Ws   = smem;
    float* buf0 = smem + WS_FLOATS;
    float* buf1 = buf0 + BUF_FLOATS;
    float* red  = buf1 + BUF_FLOATS;

    const int tid = threadIdx.x;
    const int bid = blockIdx.x;
    const int d0  = bid * 4;

    const int cp    = tid & 7;
    const int chunk = (tid >> 5) & 7;
    const int bhq   = ((tid >> 3) & 3) | ((tid >> 8) << 2);
    const int eb    = tid >> 2;
    const int edl   = tid & 3;

    pf_tile(buf0, x);
    CPA_COMMIT();
    fill_ws(Ws, Wi, d0);

    float b_i = 0.f, b_f = 0.f, b_g = 0.f, b_o = 0.f;
    if (tid < 256) {
        int d = d0 + edl;
        b_i = bias[d];
        b_f = bias[512 + d];
        b_g = bias[1024 + d];
        b_o = bias[1536 + d];
    }

    unsigned gen0 = 0;
    if (tid == 0) gen0 = g_gen;
    unsigned epoch = 0;
    __syncthreads();

    float* zx_cta = g_zx + (size_t)bid * 1024;

    for (int t = 0; t < TS; ++t) {
        const float* xt = x + (size_t)t * 32768;

        unsigned long long accA[8], accB[8];
#pragma unroll
        for (int i = 0; i < 8; ++i) { accA[i] = 0ULL; accB[i] = 0ULL; }

        pf_tile(buf1, xt + 16384);
        CPA_COMMIT();
        CPA_WAIT1();
        __syncthreads();
        gemm_tile(Ws, buf0, accA, cp, bhq, chunk);
        __syncthreads();

        int tn = (t < TS - 1) ? t + 1 : t;
        pf_tile(buf0, x + (size_t)tn * 32768);
        CPA_COMMIT();
        CPA_WAIT1();
        __syncthreads();
        gemm_tile(Ws, buf1, accB, cp, bhq, chunk);

        write_partials(red, accA, accB, cp, bhq, chunk);
        __syncthreads();

        if (tid < 256) {
            float zi = b_i, zf = b_f, zg = b_g, zo = b_o;
#pragma unroll
            for (int ch = 0; ch < 8; ++ch) {
                const float* r = &red[(ch * 64 + eb) * RED_STRIDE + edl];
                zi += r[0];
                zf += r[4];
                zg += r[8];
                zo += r[12];
            }
            *(float4*)(zx_cta + (size_t)t * NCTA * 1024 + tid * 4) =
                make_float4(zi, zf, zg, zo);
        }

        if ((t & 255) == 255) {   // bound drift: keep x_t L2-resident
            __threadfence();
            __syncthreads();
            if (tid == 0) {
                unsigned a = atomicAdd(&g_count, 1u);
                if (((a + 1u) & (NCTA - 1u)) == 0u) g_gen = g_gen + 1u;
                ++epoch;
                while ((unsigned)(g_gen - gen0) < epoch) __nanosleep(64);
            }
            __syncthreads();
        }
    }
}

// ========================= PHASE 2 KERNEL =========================
extern "C" __global__ void __launch_bounds__(NTHR, 1)
lstm_rec(const float* __restrict__ c0,
         const float* __restrict__ h0,
         const float* __restrict__ Wh,
         float* __restrict__ out,
         long long out_size) {
    extern __shared__ float smem[];
    float* Ws   = smem;
    float* buf0 = smem + WS_FLOATS;
    float* buf1 = buf0 + BUF_FLOATS;
    float* red  = buf1 + BUF_FLOATS;
    __shared__ unsigned s_fbase;

    const int tid = threadIdx.x;
    const int bid = blockIdx.x;
    const int d0  = bid * 4;

    const int cp    = tid & 7;
    const int chunk = (tid >> 5) & 7;
    const int bhq   = ((tid >> 3) & 3) | ((tid >> 8) << 2);
    const int eb    = tid >> 2;
    const int edl   = tid & 3;

    // epoch base = own flag (self-written only -> stable, replay-safe)
    if (tid == 0) s_fbase = ldflag(&g_flags[bid * 8]);

    fill_ws(Ws, Wh, d0);

    float c_reg = 0.f;
    if (tid < 256) c_reg = c0[eb * DD + d0 + edl];
    __syncthreads();
    const unsigned fbase = s_fbase;

    const float* zx_cta = g_zx + (size_t)bid * 1024;

    for (int t = 0; t < TS; ++t) {
        // prefetch this CTA's Zx[t] (no cross-CTA dependency)
        float4 zx = make_float4(0.f, 0.f, 0.f, 0.f);
        if (tid < 256)
            zx = *(const float4*)(zx_cta + (size_t)t * NCTA * 1024 + tid * 4);

        // flag wait: thread j polls producer CTA j's epoch (no atomics)
        if (t > 0 && tid < NCTA) {
            unsigned tgt = fbase + (unsigned)t;
            while ((int)(ldflag(&g_flags[tid * 8]) - tgt) < 0) __nanosleep(32);
        }
        __syncthreads();

        const float* hsrc = (t == 0) ? h0 : g_hbuf[t & 1];

        unsigned long long accA[8], accB[8];
#pragma unroll
        for (int i = 0; i < 8; ++i) { accA[i] = 0ULL; accB[i] = 0ULL; }

        pf_tile(buf0, hsrc);
        CPA_COMMIT();
        pf_tile(buf1, hsrc + 16384);
        CPA_COMMIT();

        CPA_WAIT1();
        __syncthreads();
        gemm_tile(Ws, buf0, accA, cp, bhq, chunk);

        CPA_WAIT0();
        __syncthreads();
        gemm_tile(Ws, buf1, accB, cp, bhq, chunk);

        write_partials(red, accA, accB, cp, bhq, chunk);
        __syncthreads();

        float hh = 0.f, cc = 0.f;
        if (tid < 256) {
            float zi = zx.x, zf = zx.y, zg = zx.z, zo = zx.w;
#pragma unroll
            for (int ch = 0; ch < 8; ++ch) {
                const float* r = &red[(ch * 64 + eb) * RED_STRIDE + edl];
                zi += r[0];
                zf += r[4];
                zg += r[8];
                zo += r[12];
            }
            cc = sigf(zf) * c_reg + sigf(zi) * tanhfast(zg);
            hh = sigf(zo) * tanhfast(cc);
            c_reg = cc;
            __stcg(&g_hbuf[(t + 1) & 1][eb * DD + d0 + edl], hh);
            __threadfence();   // own h stores -> L2 before flag
        }
        __syncthreads();

        if (tid == 0) __stcg(&g_flags[bid * 8], fbase + (unsigned)(t + 1));

        // ys writes off the critical inter-CTA path
        if (tid < 256) {
            int d = d0 + edl;
            out[(size_t)t * 32768 + eb * DD + d] = hh;
            if (t == TS - 1 && out_size >= 33554432LL + 65536LL) {
                out[33554432 + eb * DD + d] = cc;
                out[33554432 + 32768 + eb * DD + d] = hh;
            }
        }
    }
}

extern "C" void kernel_launch(void* const* d_in, const int* in_sizes, int n_in,
                              void* d_out, int out_size) {
    const float* x  = (const float*)d_in[0];
    const float* c0 = (const float*)d_in[1];
    const float* h0 = (const float*)d_in[2];
    const float* Wi = (const float*)d_in[3];
    const float* Wh = (const float*)d_in[4];
    const float* b  = (const float*)d_in[5];

    const int smem_bytes = (WS_FLOATS + 2 * BUF_FLOATS + RED_FLOATS) * 4;
    cudaFuncSetAttribute(lstm_zx,
                         cudaFuncAttributeMaxDynamicSharedMemorySize, smem_bytes);
    cudaFuncSetAttribute(lstm_rec,
                         cudaFuncAttributeMaxDynamicSharedMemorySize, smem_bytes);

    lstm_zx<<<NCTA, NTHR, smem_bytes>>>(x, Wi, b);
    lstm_rec<<<NCTA, NTHR, smem_bytes>>>(c0, h0, Wh, (float*)d_out,
                                         (long long)out_size);
}

// round 5
// speedup vs baseline: 1.1274x; 1.1274x over previous
#include <cuda_runtime.h>
#include <cstdint>

// LSTM T=1024, B=64, D=512 — batch x dim split: 128 CTAs = 4 batch-groups
// x 32 dim-groups. CTA tile: 16 batches x 16 dims (64 z-cols) x k=512.
// Phase 1 (lstm_zx): Zx = x@Wi + b, parallel over t. Phase 2 (lstm_rec):
// z = Zx + h@Wh; gates. h exchange: 32-producer flag wait per batch-group.

#define TS   1024
#define NCTA 128
#define NTHR 512

#define BUF_STRIDE 516                   // floats per activation row
#define BUF_FLOATS (16 * BUF_STRIDE)     // 8256 floats = 33024 B
#define WS_FLOATS  (64 * 512)            // 32768 floats = 131072 B
#define RED_STRIDE 80                    // 64 cols + 16 pad (bank-disjoint rows)
#define RED_FLOATS (4 * 16 * RED_STRIDE) // 5120 floats = 20480 B

__device__ float g_zx[(size_t)TS * NCTA * 1024];  // [t][cta][256*float4]
__device__ float g_hbuf[2][64 * 512];
__device__ unsigned g_count = 0;
__device__ volatile unsigned g_gen = 0;
__device__ unsigned g_flags[NCTA * 8];

__device__ __forceinline__ void fma2(unsigned long long& d,
                                     unsigned long long a,
                                     unsigned long long b) {
    asm volatile("fma.rn.f32x2 %0, %1, %2, %0;" : "+l"(d) : "l"(a), "l"(b));
}
__device__ __forceinline__ float sigf(float x) {
    return __fdividef(1.0f, 1.0f + __expf(-x));
}
__device__ __forceinline__ float tanhfast(float x) {
    float e = __expf(-2.0f * x);
    return __fdividef(1.0f - e, 1.0f + e);
}
__device__ __forceinline__ unsigned ldflag(const unsigned* p) {
    unsigned v;
    asm volatile("ld.global.cg.u32 %0, [%1];" : "=r"(v) : "l"(p));
    return v;
}
__device__ __forceinline__ void cpa16(float* dst, const float* src) {
    unsigned s = (unsigned)__cvta_generic_to_shared(dst);
    asm volatile("cp.async.cg.shared.global [%0], [%1], 16;" :: "r"(s), "l"(src));
}
#define CPA_COMMIT() asm volatile("cp.async.commit_group;" ::: "memory")
#define CPA_WAIT1()  asm volatile("cp.async.wait_group 1;" ::: "memory")
#define CPA_WAIT0()  asm volatile("cp.async.wait_group 0;" ::: "memory")

// stage 16 rows x 512 floats (32 KB) global -> smem (row stride 516)
__device__ __forceinline__ void pf16(float* dst, const float* gsrc) {
    int r  = threadIdx.x >> 5;      // 0..15
    int c0 = threadIdx.x & 31;
    const float* s = gsrc + r * 512;
    float* d = dst + r * BUF_STRIDE;
#pragma unroll
    for (int j = 0; j < 4; ++j) {
        int c = c0 + j * 32;        // 16B chunk 0..127
        cpa16(d + c * 4, s + c * 4);
    }
}

// Ws: 64 cols x 512 k, XOR-swizzled 16B units. col c = gate*16 + dloc.
__device__ __forceinline__ void fill_ws(float* Ws, const float* W, int d0) {
    for (int i = threadIdx.x; i < 64 * 512; i += NTHR) {
        int c = i >> 9, k = i & 511;
        int zc = ((c >> 4) << 9) + d0 + (c & 15);
        float w = W[(size_t)k * 2048 + zc];
        int kq = k >> 2;
        int u  = (kq & ~7) | ((kq ^ (c >> 1)) & 7);
        Ws[((c << 7) | u) * 4 + (k & 3)] = w;
    }
}

// thread tile: cols {2cp, 2cp+1} x rows {bq,bq+4,bq+8,bq+12} x 128 k (chunk)
__device__ __forceinline__ void gemm16(const float* __restrict__ Ws,
                                       const float* __restrict__ buf,
                                       unsigned long long* acc,
                                       int cp, int bq, int chunk) {
    const ulonglong2* wp0 = (const ulonglong2*)Ws + (2 * cp) * 128 + chunk * 32;
    const ulonglong2* wp1 = wp0 + 128;
    const ulonglong2* ap  = (const ulonglong2*)buf + bq * 129 + chunk * 32;
#pragma unroll 4
    for (int kk = 0; kk < 32; ++kk) {
        int u = (kk & ~7) | ((kk ^ cp) & 7);
        ulonglong2 w0 = wp0[u];
        ulonglong2 w1 = wp1[u];
#pragma unroll
        for (int bi = 0; bi < 4; ++bi) {
            ulonglong2 a = ap[bi * 4 * 129 + kk];
            fma2(acc[bi],     w0.x, a.x);
            fma2(acc[bi],     w0.y, a.y);
            fma2(acc[4 + bi], w1.x, a.x);
            fma2(acc[4 + bi], w1.y, a.y);
        }
    }
}

__device__ __forceinline__ void write_partials(float* red,
                                               unsigned long long* acc,
                                               int cp, int bq, int chunk) {
#pragma unroll
    for (int bi = 0; bi < 4; ++bi) {
        float2 e = *(float2*)&acc[bi];
        float2 o = *(float2*)&acc[4 + bi];
        int b = bq + 4 * bi;
        *(float2*)&red[(chunk * 16 + b) * RED_STRIDE + 2 * cp] =
            make_float2(e.x + e.y, o.x + o.y);
    }
}

// ========================= PHASE 1: Zx = x@Wi + b =========================
extern "C" __global__ void __launch_bounds__(NTHR, 1)
lstm_zx(const float* __restrict__ x,
        const float* __restrict__ Wi,
        const float* __restrict__ bias) {
    extern __shared__ float smem[];
    float* Ws   = smem;
    float* buf0 = smem + WS_FLOATS;
    float* buf1 = buf0 + BUF_FLOATS;
    float* red  = buf1 + BUF_FLOATS;

    const int tid = threadIdx.x;
    const int bid = blockIdx.x;
    const int gd  = bid & 31, gb = bid >> 5;
    const int d0  = gd * 16;

    const int lane  = tid & 31;
    const int cp    = (lane & 7) | ((tid >> 7) << 3);  // 0..31 (col pair)
    const int bq    = (lane >> 3);                     // 0..3
    const int chunk = (tid >> 5) & 3;                  // 0..3 (128-k)

    const int eb   = tid >> 4;   // reducer: batch 0..15
    const int dloc = tid & 15;   // reducer: dim 0..15

    pf16(buf0, x + gb * 8192);   // x_0 slice
    CPA_COMMIT();
    fill_ws(Ws, Wi, d0);

    float b_i = 0.f, b_f = 0.f, b_g = 0.f, b_o = 0.f;
    if (tid < 256) {
        int d = d0 + dloc;
        b_i = bias[d];
        b_f = bias[512 + d];
        b_g = bias[1024 + d];
        b_o = bias[1536 + d];
    }

    unsigned gen0 = 0;
    if (tid == 0) gen0 = g_gen;
    unsigned epoch = 0;
    __syncthreads();

    float* zx_base = g_zx + (size_t)bid * 1024;
    float* bufs[2] = {buf0, buf1};

    for (int t = 0; t < TS; ++t) {
        int tn = (t < TS - 1) ? t + 1 : t;
        pf16(bufs[(t + 1) & 1], x + (size_t)tn * 32768 + gb * 8192);
        CPA_COMMIT();
        CPA_WAIT1();
        __syncthreads();

        unsigned long long acc[8];
#pragma unroll
        for (int i = 0; i < 8; ++i) acc[i] = 0ULL;
        gemm16(Ws, bufs[t & 1], acc, cp, bq, chunk);

        write_partials(red, acc, cp, bq, chunk);
        __syncthreads();

        if (tid < 256) {
            float zi = b_i, zf = b_f, zg = b_g, zo = b_o;
#pragma unroll
            for (int ch = 0; ch < 4; ++ch) {
                const float* r = &red[(ch * 16 + eb) * RED_STRIDE + dloc];
                zi += r[0];
                zf += r[16];
                zg += r[32];
                zo += r[48];
            }
            *(float4*)(zx_base + (size_t)t * (NCTA * 1024) + tid * 4) =
                make_float4(zi, zf, zg, zo);
        }

        if ((t & 255) == 255) {  // bound CTA drift (keep x L2-resident)
            __threadfence();
            __syncthreads();
            if (tid == 0) {
                unsigned a = atomicAdd(&g_count, 1u);
                if (((a + 1u) & (NCTA - 1u)) == 0u) g_gen = g_gen + 1u;
                ++epoch;
                while ((unsigned)(g_gen - gen0) < epoch) __nanosleep(64);
            }
            __syncthreads();
        }
    }
}

// ========================= PHASE 2: recurrence =========================
extern "C" __global__ void __launch_bounds__(NTHR, 1)
lstm_rec(const float* __restrict__ c0,
         const float* __restrict__ h0,
         const float* __restrict__ Wh,
         float* __restrict__ out,
         long long out_size) {
    extern __shared__ float smem[];
    float* Ws   = smem;
    float* buf0 = smem + WS_FLOATS;
    float* red  = buf0 + 2 * BUF_FLOATS;
    __shared__ unsigned s_fbase;

    const int tid = threadIdx.x;
    const int bid = blockIdx.x;
    const int gd  = bid & 31, gb = bid >> 5;
    const int d0  = gd * 16;

    const int lane  = tid & 31;
    const int cp    = (lane & 7) | ((tid >> 7) << 3);
    const int bq    = (lane >> 3);
    const int chunk = (tid >> 5) & 3;

    const int eb   = tid >> 4;
    const int dloc = tid & 15;

    if (tid == 0) s_fbase = ldflag(&g_flags[bid * 8]);
    fill_ws(Ws, Wh, d0);

    float c_reg = 0.f;
    if (tid < 256) c_reg = c0[(gb * 16 + eb) * 512 + d0 + dloc];
    __syncthreads();
    const unsigned fbase = s_fbase;

    const float* zx_base = g_zx + (size_t)bid * 1024;

    for (int t = 0; t < TS; ++t) {
        float4 zx = make_float4(0.f, 0.f, 0.f, 0.f);
        if (tid < 256)
            zx = *(const float4*)(zx_base + (size_t)t * (NCTA * 1024) + tid * 4);

        // wait on the 32 producers of this batch-group
        if (t > 0 && tid < 32) {
            unsigned tgt = fbase + (unsigned)t;
            const unsigned* fp = &g_flags[(gb * 32 + tid) * 8];
            while ((int)(ldflag(fp) - tgt) < 0) __nanosleep(32);
        }
        __syncthreads();

        const float* hsrc = ((t == 0) ? h0 : g_hbuf[t & 1]) + gb * 8192;
        pf16(buf0, hsrc);
        CPA_COMMIT();
        CPA_WAIT0();
        __syncthreads();

        unsigned long long acc[8];
#pragma unroll
        for (int i = 0; i < 8; ++i) acc[i] = 0ULL;
        gemm16(Ws, buf0, acc, cp, bq, chunk);

        write_partials(red, acc, cp, bq, chunk);
        __syncthreads();

        float hh = 0.f, cc = 0.f;
        if (tid < 256) {
            float zi = zx.x, zf = zx.y, zg = zx.z, zo = zx.w;
#pragma unroll
            for (int ch = 0; ch < 4; ++ch) {
                const float* r = &red[(ch * 16 + eb) * RED_STRIDE + dloc];
                zi += r[0];
                zf += r[16];
                zg += r[32];
                zo += r[48];
            }
            cc = sigf(zf) * c_reg + sigf(zi) * tanhfast(zg);
            hh = sigf(zo) * tanhfast(cc);
            c_reg = cc;
            __stcg(&g_hbuf[(t + 1) & 1][(gb * 16 + eb) * 512 + d0 + dloc], hh);
            __threadfence();
        }
        __syncthreads();

        if (tid == 0) __stcg(&g_flags[bid * 8], fbase + (unsigned)(t + 1));

        if (tid < 256) {
            int d = d0 + dloc;
            int bgl = gb * 16 + eb;
            out[(size_t)t * 32768 + bgl * 512 + d] = hh;
            if (t == TS - 1 && out_size >= 33554432LL + 65536LL) {
                out[33554432 + bgl * 512 + d] = cc;
                out[33554432 + 32768 + bgl * 512 + d] = hh;
            }
        }
    }
}

extern "C" void kernel_launch(void* const* d_in, const int* in_sizes, int n_in,
                              void* d_out, int out_size) {
    const float* x  = (const float*)d_in[0];
    const float* c0 = (const float*)d_in[1];
    const float* h0 = (const float*)d_in[2];
    const float* Wi = (const float*)d_in[3];
    const float* Wh = (const float*)d_in[4];
    const float* b  = (const float*)d_in[5];

    const int smem_bytes = (WS_FLOATS + 2 * BUF_FLOATS + RED_FLOATS) * 4; // 217600
    cudaFuncSetAttribute(lstm_zx,
                         cudaFuncAttributeMaxDynamicSharedMemorySize, smem_bytes);
    cudaFuncSetAttribute(lstm_rec,
                         cudaFuncAttributeMaxDynamicSharedMemorySize, smem_bytes);

    lstm_zx<<<NCTA, NTHR, smem_bytes>>>(x, Wi, b);
    lstm_rec<<<NCTA, NTHR, smem_bytes>>>(c0, h0, Wh, (float*)d_out,
                                         (long long)out_size);
}

// round 6
// speedup vs baseline: 1.4098x; 1.2505x over previous
#include <cuda_runtime.h>
#include <cstdint>

// LSTM T=1024, B=64, D=512 — batch x dim split (4 x 32), CTA = 16 b x 16 d.
// Thread tile: 4 cols x 4 batches x 64 k (16 accs, 8 chunks). f32x2 FMA.
// lstm_zx: Zx = x@Wi + b (parallel). lstm_rec: z = Zx + h@Wh; gates.

#define TS   1024
#define NCTA 128
#define NTHR 512

#define BUF_STRIDE 516                    // floats per activation row
#define BUF_FLOATS (16 * BUF_STRIDE)      // 8256 floats
#define WS_FLOATS  (64 * 512)             // 32768 floats
#define RED_STRIDE 68                     // 64 cols + 4 pad
#define RED_FLOATS (8 * 16 * RED_STRIDE)  // 8704 floats

__device__ float g_zx[(size_t)TS * NCTA * 1024];  // [t][cta][256*float4]
__device__ float g_hbuf[2][64 * 512];
__device__ unsigned g_count = 0;
__device__ volatile unsigned g_gen = 0;
__device__ unsigned g_flags[NCTA * 8];

__device__ __forceinline__ void fma2(unsigned long long& d,
                                     unsigned long long a,
                                     unsigned long long b) {
    asm volatile("fma.rn.f32x2 %0, %1, %2, %0;" : "+l"(d) : "l"(a), "l"(b));
}
__device__ __forceinline__ float sigf(float x) {
    return __fdividef(1.0f, 1.0f + __expf(-x));
}
__device__ __forceinline__ float tanhfast(float x) {
    float e = __expf(-2.0f * x);
    return __fdividef(1.0f - e, 1.0f + e);
}
__device__ __forceinline__ unsigned ldflag(const unsigned* p) {
    unsigned v;
    asm volatile("ld.global.cg.u32 %0, [%1];" : "=r"(v) : "l"(p));
    return v;
}
__device__ __forceinline__ void cpa16(float* dst, const float* src) {
    unsigned s = (unsigned)__cvta_generic_to_shared(dst);
    asm volatile("cp.async.cg.shared.global [%0], [%1], 16;" :: "r"(s), "l"(src));
}
#define CPA_COMMIT() asm volatile("cp.async.commit_group;" ::: "memory")
#define CPA_WAIT1()  asm volatile("cp.async.wait_group 1;" ::: "memory")
#define CPA_WAIT0()  asm volatile("cp.async.wait_group 0;" ::: "memory")

// stage 16 rows x 512 floats (32 KB) global -> smem (row stride 516)
__device__ __forceinline__ void pf16(float* dst, const float* gsrc) {
    int r  = threadIdx.x >> 5;
    int c0 = threadIdx.x & 31;
    const float* s = gsrc + r * 512;
    float* d = dst + r * BUF_STRIDE;
#pragma unroll
    for (int j = 0; j < 4; ++j) {
        int c = c0 + j * 32;
        cpa16(d + c * 4, s + c * 4);
    }
}

// Ws: 64 cols x 512 k, 16B-unit swizzle keyed on col-quad (c>>2)
__device__ __forceinline__ void fill_ws(float* Ws, const float* W, int d0) {
    for (int i = threadIdx.x; i < 64 * 512; i += NTHR) {
        int c = i >> 9, k = i & 511;
        int zc = ((c >> 4) << 9) + d0 + (c & 15);
        float w = W[(size_t)k * 2048 + zc];
        int kq = k >> 2;
        int u  = (kq & ~7) | ((kq ^ (c >> 2)) & 7);
        Ws[((c << 7) | u) * 4 + (k & 3)] = w;
    }
}

// thread tile: cols {4cq..4cq+3} x rows {bq,bq+4,bq+8,bq+12} x 64 k (chunk)
// acc[bi*4+j] => (row bq+4bi, col 4cq+j)
__device__ __forceinline__ void gemm44(const float* __restrict__ Ws,
                                       const float* __restrict__ buf,
                                       unsigned long long* acc,
                                       int cq, int bq, int chunk) {
    const ulonglong2* wb = (const ulonglong2*)Ws + (4 * cq) * 128;
    const ulonglong2* ap = (const ulonglong2*)buf + bq * 129 + chunk * 16;
    const int kq0 = chunk * 16;
#pragma unroll 4
    for (int kk = 0; kk < 16; ++kk) {
        int kq = kq0 + kk;
        int u  = (kq & ~7) | ((kq ^ cq) & 7);
        ulonglong2 w0 = wb[u];
        ulonglong2 w1 = wb[128 + u];
        ulonglong2 w2 = wb[256 + u];
        ulonglong2 w3 = wb[384 + u];
#pragma unroll
        for (int bi = 0; bi < 4; ++bi) {
            ulonglong2 a = ap[bi * 516 + kk];
            unsigned long long* ac = acc + bi * 4;
            fma2(ac[0], w0.x, a.x);
            fma2(ac[0], w0.y, a.y);
            fma2(ac[1], w1.x, a.x);
            fma2(ac[1], w1.y, a.y);
            fma2(ac[2], w2.x, a.x);
            fma2(ac[2], w2.y, a.y);
            fma2(ac[3], w3.x, a.x);
            fma2(ac[3], w3.y, a.y);
        }
    }
}

__device__ __forceinline__ void write_partials(float* red,
                                               unsigned long long* acc,
                                               int cq, int bq, int chunk) {
#pragma unroll
    for (int bi = 0; bi < 4; ++bi) {
        float2 s0 = *(float2*)&acc[bi * 4 + 0];
        float2 s1 = *(float2*)&acc[bi * 4 + 1];
        float2 s2 = *(float2*)&acc[bi * 4 + 2];
        float2 s3 = *(float2*)&acc[bi * 4 + 3];
        int row = chunk * 16 + bq + 4 * bi;
        *(float4*)&red[row * RED_STRIDE + 4 * cq] =
            make_float4(s0.x + s0.y, s1.x + s1.y, s2.x + s2.y, s3.x + s3.y);
    }
}

// ========================= PHASE 1: Zx = x@Wi + b =========================
extern "C" __global__ void __launch_bounds__(NTHR, 1)
lstm_zx(const float* __restrict__ x,
        const float* __restrict__ Wi,
        const float* __restrict__ bias) {
    extern __shared__ float smem[];
    float* Ws   = smem;
    float* buf0 = smem + WS_FLOATS;
    float* buf1 = buf0 + BUF_FLOATS;
    float* red  = buf1 + BUF_FLOATS;

    const int tid = threadIdx.x;
    const int bid = blockIdx.x;
    const int gd  = bid & 31, gb = bid >> 5;
    const int d0  = gd * 16;

    const int lane  = tid & 31;
    const int warp  = tid >> 5;
    const int cq    = (lane & 7) | ((warp & 1) << 3);  // 0..15
    const int bq    = lane >> 3;                       // 0..3
    const int chunk = warp >> 1;                       // 0..7

    const int eb   = tid >> 4;
    const int dloc = tid & 15;

    pf16(buf0, x + gb * 8192);
    CPA_COMMIT();
    fill_ws(Ws, Wi, d0);

    float b_i = 0.f, b_f = 0.f, b_g = 0.f, b_o = 0.f;
    if (tid < 256) {
        int d = d0 + dloc;
        b_i = bias[d];
        b_f = bias[512 + d];
        b_g = bias[1024 + d];
        b_o = bias[1536 + d];
    }

    unsigned gen0 = 0;
    if (tid == 0) gen0 = g_gen;
    unsigned epoch = 0;
    __syncthreads();

    float* zx_base = g_zx + (size_t)bid * 1024;
    float* bufs[2] = {buf0, buf1};

    for (int t = 0; t < TS; ++t) {
        int tn = (t < TS - 1) ? t + 1 : t;
        pf16(bufs[(t + 1) & 1], x + (size_t)tn * 32768 + gb * 8192);
        CPA_COMMIT();
        CPA_WAIT1();
        __syncthreads();

        unsigned long long acc[16];
#pragma unroll
        for (int i = 0; i < 16; ++i) acc[i] = 0ULL;
        gemm44(Ws, bufs[t & 1], acc, cq, bq, chunk);

        write_partials(red, acc, cq, bq, chunk);
        __syncthreads();

        if (tid < 256) {
            float zi = b_i, zf = b_f, zg = b_g, zo = b_o;
#pragma unroll
            for (int ch = 0; ch < 8; ++ch) {
                const float* r = &red[(ch * 16 + eb) * RED_STRIDE + dloc];
                zi += r[0];
                zf += r[16];
                zg += r[32];
                zo += r[48];
            }
            *(float4*)(zx_base + (size_t)t * (NCTA * 1024) + tid * 4) =
                make_float4(zi, zf, zg, zo);
        }

        if ((t & 255) == 255) {   // bound drift (keep x L2-resident)
            __threadfence();
            __syncthreads();
            if (tid == 0) {
                unsigned a = atomicAdd(&g_count, 1u);
                if (((a + 1u) & (NCTA - 1u)) == 0u) g_gen = g_gen + 1u;
                ++epoch;
                while ((unsigned)(g_gen - gen0) < epoch) __nanosleep(64);
            }
            __syncthreads();
        }
    }
}

// ========================= PHASE 2: recurrence =========================
extern "C" __global__ void __launch_bounds__(NTHR, 1)
lstm_rec(const float* __restrict__ c0,
         const float* __restrict__ h0,
         const float* __restrict__ Wh,
         float* __restrict__ out,
         long long out_size) {
    extern __shared__ float smem[];
    float* Ws   = smem;
    float* buf0 = smem + WS_FLOATS;
    float* red  = buf0 + 2 * BUF_FLOATS;
    __shared__ unsigned s_fbase;

    const int tid = threadIdx.x;
    const int bid = blockIdx.x;
    const int gd  = bid & 31, gb = bid >> 5;
    const int d0  = gd * 16;

    const int lane  = tid & 31;
    const int warp  = tid >> 5;
    const int cq    = (lane & 7) | ((warp & 1) << 3);
    const int bq    = lane >> 3;
    const int chunk = warp >> 1;

    const int eb   = tid >> 4;
    const int dloc = tid & 15;

    if (tid == 0) s_fbase = ldflag(&g_flags[bid * 8]);
    fill_ws(Ws, Wh, d0);

    float c_reg = 0.f;
    if (tid < 256) c_reg = c0[(gb * 16 + eb) * 512 + d0 + dloc];
    __syncthreads();
    const unsigned fbase = s_fbase;

    const float* zx_base = g_zx + (size_t)bid * 1024;

    for (int t = 0; t < TS; ++t) {
        float4 zx = make_float4(0.f, 0.f, 0.f, 0.f);
        if (tid < 256)
            zx = *(const float4*)(zx_base + (size_t)t * (NCTA * 1024) + tid * 4);

        // wait on the 32 producers of this batch-group
        if (t > 0 && tid < 32) {
            unsigned tgt = fbase + (unsigned)t;
            const unsigned* fp = &g_flags[(gb * 32 + tid) * 8];
            while ((int)(ldflag(fp) - tgt) < 0) __nanosleep(32);
        }
        __syncthreads();

        const float* hsrc = ((t == 0) ? h0 : g_hbuf[t & 1]) + gb * 8192;
        pf16(buf0, hsrc);
        CPA_COMMIT();
        CPA_WAIT0();
        __syncthreads();

        unsigned long long acc[16];
#pragma unroll
        for (int i = 0; i < 16; ++i) acc[i] = 0ULL;
        gemm44(Ws, buf0, acc, cq, bq, chunk);

        write_partials(red, acc, cq, bq, chunk);
        __syncthreads();

        float hh = 0.f, cc = 0.f;
        if (tid < 256) {
            float zi = zx.x, zf = zx.y, zg = zx.z, zo = zx.w;
#pragma unroll
            for (int ch = 0; ch < 8; ++ch) {
                const float* r = &red[(ch * 16 + eb) * RED_STRIDE + dloc];
                zi += r[0];
                zf += r[16];
                zg += r[32];
                zo += r[48];
            }
            cc = sigf(zf) * c_reg + sigf(zi) * tanhfast(zg);
            hh = sigf(zo) * tanhfast(cc);
            c_reg = cc;
            __stcg(&g_hbuf[(t + 1) & 1][(gb * 16 + eb) * 512 + d0 + dloc], hh);
        }
        __syncthreads();   // h stores done (cta-scope) before release fence

        if (tid == 0) {
            asm volatile("fence.acq_rel.gpu;" ::: "memory");  // cumulative release
            __stcg(&g_flags[bid * 8], fbase + (unsigned)(t + 1));
        }

        // ys / final-state writes off the inter-CTA critical path
        if (tid < 256) {
            int d = d0 + dloc;
            int bgl = gb * 16 + eb;
            out[(size_t)t * 32768 + bgl * 512 + d] = hh;
            if (t == TS - 1 && out_size >= 33554432LL + 65536LL) {
                out[33554432 + bgl * 512 + d] = cc;
                out[33554432 + 32768 + bgl * 512 + d] = hh;
            }
        }
    }
}

extern "C" void kernel_launch(void* const* d_in, const int* in_sizes, int n_in,
                              void* d_out, int out_size) {
    const float* x  = (const float*)d_in[0];
    const float* c0 = (const float*)d_in[1];
    const float* h0 = (const float*)d_in[2];
    const float* Wi = (const float*)d_in[3];
    const float* Wh = (const float*)d_in[4];
    const float* b  = (const float*)d_in[5];

    const int smem_bytes = (WS_FLOATS + 2 * BUF_FLOATS + RED_FLOATS) * 4; // 231936
    cudaFuncSetAttribute(lstm_zx,
                         cudaFuncAttributeMaxDynamicSharedMemorySize, smem_bytes);
    cudaFuncSetAttribute(lstm_rec,
                         cudaFuncAttributeMaxDynamicSharedMemorySize, smem_bytes);

    lstm_zx<<<NCTA, NTHR, smem_bytes>>>(x, Wi, b);
    lstm_rec<<<NCTA, NTHR, smem_bytes>>>(c0, h0, Wh, (float*)d_out,
                                         (long long)out_size);
}

// round 7
// speedup vs baseline: 1.4788x; 1.0489x over previous
#include <cuda_runtime.h>
#include <cstdint>

// LSTM T=1024, B=64, D=512 — batch x dim split (4 x 32), CTA = 16 b x 16 d.
// Thread tile: 4 cols x 4 batches x 64 k (16 accs, 8 chunks). f32x2 FMA.
// R7: non-volatile FMA asm (allow ptxas load pipelining) + full kk unroll.

#define TS   1024
#define NCTA 128
#define NTHR 512

#define BUF_STRIDE 516                    // floats per activation row
#define BUF_FLOATS (16 * BUF_STRIDE)      // 8256 floats
#define WS_FLOATS  (64 * 512)             // 32768 floats
#define RED_STRIDE 68                     // 64 cols + 4 pad
#define RED_FLOATS (8 * 16 * RED_STRIDE)  // 8704 floats

__device__ float g_zx[(size_t)TS * NCTA * 1024];  // [t][cta][256*float4]
__device__ float g_hbuf[2][64 * 512];
__device__ unsigned g_count = 0;
__device__ volatile unsigned g_gen = 0;
__device__ unsigned g_flags[NCTA * 8];

// NOTE: non-volatile on purpose — pure register math, lets the compiler
// software-pipeline shared loads across FMA bursts.
__device__ __forceinline__ void fma2(unsigned long long& d,
                                     unsigned long long a,
                                     unsigned long long b) {
    asm("fma.rn.f32x2 %0, %1, %2, %0;" : "+l"(d) : "l"(a), "l"(b));
}
__device__ __forceinline__ float sigf(float x) {
    return __fdividef(1.0f, 1.0f + __expf(-x));
}
__device__ __forceinline__ float tanhfast(float x) {
    float e = __expf(-2.0f * x);
    return __fdividef(1.0f - e, 1.0f + e);
}
__device__ __forceinline__ unsigned ldflag(const unsigned* p) {
    unsigned v;
    asm volatile("ld.global.cg.u32 %0, [%1];" : "=r"(v) : "l"(p));
    return v;
}
__device__ __forceinline__ void cpa16(float* dst, const float* src) {
    unsigned s = (unsigned)__cvta_generic_to_shared(dst);
    asm volatile("cp.async.cg.shared.global [%0], [%1], 16;" :: "r"(s), "l"(src));
}
#define CPA_COMMIT() asm volatile("cp.async.commit_group;" ::: "memory")
#define CPA_WAIT1()  asm volatile("cp.async.wait_group 1;" ::: "memory")
#define CPA_WAIT0()  asm volatile("cp.async.wait_group 0;" ::: "memory")

// stage 16 rows x 512 floats (32 KB) global -> smem (row stride 516)
__device__ __forceinline__ void pf16(float* dst, const float* gsrc) {
    int r  = threadIdx.x >> 5;
    int c0 = threadIdx.x & 31;
    const float* s = gsrc + r * 512;
    float* d = dst + r * BUF_STRIDE;
#pragma unroll
    for (int j = 0; j < 4; ++j) {
        int c = c0 + j * 32;
        cpa16(d + c * 4, s + c * 4);
    }
}

// Ws: 64 cols x 512 k, 16B-unit swizzle keyed on col-quad (c>>2)
__device__ __forceinline__ void fill_ws(float* Ws, const float* W, int d0) {
    for (int i = threadIdx.x; i < 64 * 512; i += NTHR) {
        int c = i >> 9, k = i & 511;
        int zc = ((c >> 4) << 9) + d0 + (c & 15);
        float w = W[(size_t)k * 2048 + zc];
        int kq = k >> 2;
        int u  = (kq & ~7) | ((kq ^ (c >> 2)) & 7);
        Ws[((c << 7) | u) * 4 + (k & 3)] = w;
    }
}

// thread tile: cols {4cq..4cq+3} x rows {bq,bq+4,bq+8,bq+12} x 64 k (chunk)
__device__ __forceinline__ void gemm44(const float* __restrict__ Ws,
                                       const float* __restrict__ buf,
                                       unsigned long long* acc,
                                       int cq, int bq, int chunk) {
    const ulonglong2* wb = (const ulonglong2*)Ws + (4 * cq) * 128;
    const ulonglong2* ap = (const ulonglong2*)buf + bq * 129 + chunk * 16;
    const int kq0 = chunk * 16;
#pragma unroll
    for (int kk = 0; kk < 16; ++kk) {
        int kq = kq0 + kk;
        int u  = (kq & ~7) | ((kq ^ cq) & 7);
        ulonglong2 w0 = wb[u];
        ulonglong2 w1 = wb[128 + u];
        ulonglong2 w2 = wb[256 + u];
        ulonglong2 w3 = wb[384 + u];
#pragma unroll
        for (int bi = 0; bi < 4; ++bi) {
            ulonglong2 a = ap[bi * 516 + kk];
            unsigned long long* ac = acc + bi * 4;
            fma2(ac[0], w0.x, a.x);
            fma2(ac[0], w0.y, a.y);
            fma2(ac[1], w1.x, a.x);
            fma2(ac[1], w1.y, a.y);
            fma2(ac[2], w2.x, a.x);
            fma2(ac[2], w2.y, a.y);
            fma2(ac[3], w3.x, a.x);
            fma2(ac[3], w3.y, a.y);
        }
    }
}

__device__ __forceinline__ void write_partials(float* red,
                                               unsigned long long* acc,
                                               int cq, int bq, int chunk) {
#pragma unroll
    for (int bi = 0; bi < 4; ++bi) {
        float2 s0 = *(float2*)&acc[bi * 4 + 0];
        float2 s1 = *(float2*)&acc[bi * 4 + 1];
        float2 s2 = *(float2*)&acc[bi * 4 + 2];
        float2 s3 = *(float2*)&acc[bi * 4 + 3];
        int row = chunk * 16 + bq + 4 * bi;
        *(float4*)&red[row * RED_STRIDE + 4 * cq] =
            make_float4(s0.x + s0.y, s1.x + s1.y, s2.x + s2.y, s3.x + s3.y);
    }
}

// ========================= PHASE 1: Zx = x@Wi + b =========================
extern "C" __global__ void __launch_bounds__(NTHR, 1)
lstm_zx(const float* __restrict__ x,
        const float* __restrict__ Wi,
        const float* __restrict__ bias) {
    extern __shared__ float smem[];
    float* Ws   = smem;
    float* buf0 = smem + WS_FLOATS;
    float* buf1 = buf0 + BUF_FLOATS;
    float* red  = buf1 + BUF_FLOATS;

    const int tid = threadIdx.x;
    const int bid = blockIdx.x;
    const int gd  = bid & 31, gb = bid >> 5;
    const int d0  = gd * 16;

    const int lane  = tid & 31;
    const int warp  = tid >> 5;
    const int cq    = (lane & 7) | ((warp & 1) << 3);
    const int bq    = lane >> 3;
    const int chunk = warp >> 1;

    const int eb   = tid >> 4;
    const int dloc = tid & 15;

    pf16(buf0, x + gb * 8192);
    CPA_COMMIT();
    fill_ws(Ws, Wi, d0);

    float b_i = 0.f, b_f = 0.f, b_g = 0.f, b_o = 0.f;
    if (tid < 256) {
        int d = d0 + dloc;
        b_i = bias[d];
        b_f = bias[512 + d];
        b_g = bias[1024 + d];
        b_o = bias[1536 + d];
    }

    unsigned gen0 = 0;
    if (tid == 0) gen0 = g_gen;
    unsigned epoch = 0;
    __syncthreads();

    float* zx_base = g_zx + (size_t)bid * 1024;
    float* bufs[2] = {buf0, buf1};

    for (int t = 0; t < TS; ++t) {
        int tn = (t < TS - 1) ? t + 1 : t;
        pf16(bufs[(t + 1) & 1], x + (size_t)tn * 32768 + gb * 8192);
        CPA_COMMIT();
        CPA_WAIT1();
        __syncthreads();

        unsigned long long acc[16];
#pragma unroll
        for (int i = 0; i < 16; ++i) acc[i] = 0ULL;
        gemm44(Ws, bufs[t & 1], acc, cq, bq, chunk);

        write_partials(red, acc, cq, bq, chunk);
        __syncthreads();

        if (tid < 256) {
            float zi = b_i, zf = b_f, zg = b_g, zo = b_o;
#pragma unroll
            for (int ch = 0; ch < 8; ++ch) {
                const float* r = &red[(ch * 16 + eb) * RED_STRIDE + dloc];
                zi += r[0];
                zf += r[16];
                zg += r[32];
                zo += r[48];
            }
            *(float4*)(zx_base + (size_t)t * (NCTA * 1024) + tid * 4) =
                make_float4(zi, zf, zg, zo);
        }

        if ((t & 255) == 255) {   // bound drift (keep x L2-resident)
            __threadfence();
            __syncthreads();
            if (tid == 0) {
                unsigned a = atomicAdd(&g_count, 1u);
                if (((a + 1u) & (NCTA - 1u)) == 0u) g_gen = g_gen + 1u;
                ++epoch;
                while ((unsigned)(g_gen - gen0) < epoch) __nanosleep(64);
            }
            __syncthreads();
        }
    }
}

// ========================= PHASE 2: recurrence =========================
extern "C" __global__ void __launch_bounds__(NTHR, 1)
lstm_rec(const float* __restrict__ c0,
         const float* __restrict__ h0,
         const float* __restrict__ Wh,
         float* __restrict__ out,
         long long out_size) {
    extern __shared__ float smem[];
    float* Ws   = smem;
    float* buf0 = smem + WS_FLOATS;
    float* red  = buf0 + 2 * BUF_FLOATS;
    __shared__ unsigned s_fbase;

    const int tid = threadIdx.x;
    const int bid = blockIdx.x;
    const int gd  = bid & 31, gb = bid >> 5;
    const int d0  = gd * 16;

    const int lane  = tid & 31;
    const int warp  = tid >> 5;
    const int cq    = (lane & 7) | ((warp & 1) << 3);
    const int bq    = lane >> 3;
    const int chunk = warp >> 1;

    const int eb   = tid >> 4;
    const int dloc = tid & 15;

    if (tid == 0) s_fbase = ldflag(&g_flags[bid * 8]);
    fill_ws(Ws, Wh, d0);

    float c_reg = 0.f;
    if (tid < 256) c_reg = c0[(gb * 16 + eb) * 512 + d0 + dloc];
    __syncthreads();
    const unsigned fbase = s_fbase;

    const float* zx_base = g_zx + (size_t)bid * 1024;

    for (int t = 0; t < TS; ++t) {
        float4 zx = make_float4(0.f, 0.f, 0.f, 0.f);
        if (tid < 256)
            zx = *(const float4*)(zx_base + (size_t)t * (NCTA * 1024) + tid * 4);

        // wait on the 32 producers of this batch-group
        if (t > 0 && tid < 32) {
            unsigned tgt = fbase + (unsigned)t;
            const unsigned* fp = &g_flags[(gb * 32 + tid) * 8];
            while ((int)(ldflag(fp) - tgt) < 0) __nanosleep(32);
        }
        __syncthreads();

        const float* hsrc = ((t == 0) ? h0 : g_hbuf[t & 1]) + gb * 8192;
        pf16(buf0, hsrc);
        CPA_COMMIT();
        CPA_WAIT0();
        __syncthreads();

        unsigned long long acc[16];
#pragma unroll
        for (int i = 0; i < 16; ++i) acc[i] = 0ULL;
        gemm44(Ws, buf0, acc, cq, bq, chunk);

        write_partials(red, acc, cq, bq, chunk);
        __syncthreads();

        float hh = 0.f, cc = 0.f;
        if (tid < 256) {
            float zi = zx.x, zf = zx.y, zg = zx.z, zo = zx.w;
#pragma unroll
            for (int ch = 0; ch < 8; ++ch) {
                const float* r = &red[(ch * 16 + eb) * RED_STRIDE + dloc];
                zi += r[0];
                zf += r[16];
                zg += r[32];
                zo += r[48];
            }
            cc = sigf(zf) * c_reg + sigf(zi) * tanhfast(zg);
            hh = sigf(zo) * tanhfast(cc);
            c_reg = cc;
            __stcg(&g_hbuf[(t + 1) & 1][(gb * 16 + eb) * 512 + d0 + dloc], hh);
        }
        __syncthreads();   // h stores done before release fence

        if (tid == 0) {
            asm volatile("fence.acq_rel.gpu;" ::: "memory");
            __stcg(&g_flags[bid * 8], fbase + (unsigned)(t + 1));
        }

        if (tid < 256) {
            int d = d0 + dloc;
            int bgl = gb * 16 + eb;
            out[(size_t)t * 32768 + bgl * 512 + d] = hh;
            if (t == TS - 1 && out_size >= 33554432LL + 65536LL) {
                out[33554432 + bgl * 512 + d] = cc;
                out[33554432 + 32768 + bgl * 512 + d] = hh;
            }
        }
    }
}

extern "C" void kernel_launch(void* const* d_in, const int* in_sizes, int n_in,
                              void* d_out, int out_size) {
    const float* x  = (const float*)d_in[0];
    const float* c0 = (const float*)d_in[1];
    const float* h0 = (const float*)d_in[2];
    const float* Wi = (const float*)d_in[3];
    const float* Wh = (const float*)d_in[4];
    const float* b  = (const float*)d_in[5];

    const int smem_bytes = (WS_FLOATS + 2 * BUF_FLOATS + RED_FLOATS) * 4; // 231936
    cudaFuncSetAttribute(lstm_zx,
                         cudaFuncAttributeMaxDynamicSharedMemorySize, smem_bytes);
    cudaFuncSetAttribute(lstm_rec,
                         cudaFuncAttributeMaxDynamicSharedMemorySize, smem_bytes);

    lstm_zx<<<NCTA, NTHR, smem_bytes>>>(x, Wi, b);
    lstm_rec<<<NCTA, NTHR, smem_bytes>>>(c0, h0, Wh, (float*)d_out,
                                         (long long)out_size);
}

// round 9
// speedup vs baseline: 1.9544x; 1.3217x over previous
#include <cuda_runtime.h>
#include <cuda_bf16.h>
#include <cstdint>

// LSTM T=1024, B=64, D=512.
// Phase 1 (lstm_zx): HMMA (mma.sync m16n8k16 bf16, 3-pass hi/lo split)
//                    Zx = x@Wi + b. CTA = 16 batches x 16 dims, tiles of 8 t.
// Phase 2 (lstm_rec): SIMT recurrence z = Zx + h@Wh (unchanged from R7).

#define TS   1024
#define NCTA 128
#define NTHR 512

// ---- rec (SIMT) constants ----
#define BUF_STRIDE 516
#define BUF_FLOATS (16 * BUF_STRIDE)
#define WS_FLOATS  (64 * 512)
#define RED_STRIDE 68
#define RED_FLOATS (8 * 16 * RED_STRIDE)

// ---- zx (HMMA) smem layout (bytes) ----
// W: 64 cols x 520 b16 (stride 1040 B), hi + lo
// A chunk: 128 rows x 72 b16 (stride 144 B), hi + lo, double buffered
#define ZW_HI   0         // 66560
#define ZW_LO   66560     // 66560  -> 133120
#define ZA_HI0  133120    // 18432
#define ZA_LO0  151552    // 18432
#define ZA_HI1  169984    // 18432
#define ZA_LO1  188416    // 18432 -> 206848
#define ZBIAS   206848    // 64 floats = 256
#define ZX_SMEM 207104

__device__ float g_zx[(size_t)TS * NCTA * 1024];  // [t][cta][eb][dloc][gate]
__device__ float g_hbuf[2][64 * 512];
__device__ unsigned g_count = 0;
__device__ volatile unsigned g_gen = 0;
__device__ unsigned g_flags[NCTA * 8];

// ===================== common helpers =====================
__device__ __forceinline__ void fma2(unsigned long long& d,
                                     unsigned long long a,
                                     unsigned long long b) {
    asm("fma.rn.f32x2 %0, %1, %2, %0;" : "+l"(d) : "l"(a), "l"(b));
}
__device__ __forceinline__ float sigf(float x) {
    return __fdividef(1.0f, 1.0f + __expf(-x));
}
__device__ __forceinline__ float tanhfast(float x) {
    float e = __expf(-2.0f * x);
    return __fdividef(1.0f - e, 1.0f + e);
}
__device__ __forceinline__ unsigned ldflag(const unsigned* p) {
    unsigned v;
    asm volatile("ld.global.cg.u32 %0, [%1];" : "=r"(v) : "l"(p));
    return v;
}
__device__ __forceinline__ void cpa16(float* dst, const float* src) {
    unsigned s = (unsigned)__cvta_generic_to_shared(dst);
    asm volatile("cp.async.cg.shared.global [%0], [%1], 16;" :: "r"(s), "l"(src));
}
#define CPA_COMMIT() asm volatile("cp.async.commit_group;" ::: "memory")
#define CPA_WAIT0()  asm volatile("cp.async.wait_group 0;" ::: "memory")

// ===================== HMMA helpers =====================
__device__ __forceinline__ void ldm4(uint32_t* r, uint32_t addr) {
    asm volatile("ldmatrix.sync.aligned.m8n8.x4.shared.b16 {%0,%1,%2,%3}, [%4];"
                 : "=r"(r[0]), "=r"(r[1]), "=r"(r[2]), "=r"(r[3]) : "r"(addr));
}
__device__ __forceinline__ void mma16816(float* d, const uint32_t* a,
                                         const uint32_t* b) {
    asm("mma.sync.aligned.m16n8k16.row.col.f32.bf16.bf16.f32 "
        "{%0,%1,%2,%3}, {%4,%5,%6,%7}, {%8,%9}, {%0,%1,%2,%3};"
        : "+f"(d[0]), "+f"(d[1]), "+f"(d[2]), "+f"(d[3])
        : "r"(a[0]), "r"(a[1]), "r"(a[2]), "r"(a[3]), "r"(b[0]), "r"(b[1]));
}
__device__ __forceinline__ uint32_t pack_hi_lo(float a, float b, uint32_t& lo) {
    __nv_bfloat16 ha = __float2bfloat16(a), hb = __float2bfloat16(b);
    float la = a - __bfloat162float(ha);
    float lb = b - __bfloat162float(hb);
    __nv_bfloat162 l2 = __floats2bfloat162_rn(la, lb);
    lo = *(uint32_t*)&l2;
    __nv_bfloat162 h2;
    h2.x = ha; h2.y = hb;
    return *(uint32_t*)&h2;
}

// ========================= PHASE 1: HMMA Zx =========================
extern "C" __global__ void __launch_bounds__(NTHR, 1)
lstm_zx(const float* __restrict__ x,     // [T,B,D]
        const float* __restrict__ Wi,    // [D,4D]
        const float* __restrict__ bias) {
    extern __shared__ char sm[];
    const uint32_t smb = (uint32_t)__cvta_generic_to_shared(sm);
    float* sbias = (float*)(sm + ZBIAS);

    const int tid = threadIdx.x;
    const int bid = blockIdx.x;
    const int gd = bid & 31, gb = bid >> 5;
    const int d0 = gd * 16;
    const int wid = tid >> 5;
    const int L   = tid & 31;

    // one-time: weights -> bf16 hi/lo, [col][k], row stride 520 b16
    for (int i = tid; i < 64 * 512; i += NTHR) {
        int c = i >> 9, k = i & 511;
        int zc = ((c >> 4) << 9) + d0 + (c & 15);
        float w = Wi[(size_t)k * 2048 + zc];
        __nv_bfloat16 h = __float2bfloat16(w);
        __nv_bfloat16 l = __float2bfloat16(w - __bfloat162float(h));
        int off = c * 1040 + k * 2;
        *(__nv_bfloat16*)(sm + ZW_HI + off) = h;
        *(__nv_bfloat16*)(sm + ZW_LO + off) = l;
    }
    if (tid < 64)
        sbias[tid] = bias[(tid >> 4) * 512 + d0 + (tid & 15)];

    // warp tiling: 4 (m) x 4 (n); warp tile 32 rows x 16 cols
    const int mr = (wid & 3) * 32;
    const int nb = (wid >> 2) * 16;

    // ldmatrix lane offsets
    const uint32_t amr = (uint32_t)((mr + (L & 15)) * 144 + (L >> 4) * 16);
    const uint32_t boff =
        (uint32_t)((nb + (L & 7) + ((L >> 4) & 1) * 8) * 1040 +
                   ((L >> 3) & 1) * 16);
    const uint32_t bhi_lane = smb + ZW_HI + boff;
    const uint32_t blo_lane = smb + ZW_LO + boff;

    // convert roles
    const int r = tid >> 2;          // A row 0..127
    const int q = tid & 3;           // 16-float group
    const float* xrow_p = x + (size_t)(r >> 4) * 32768 +
                          (size_t)(gb * 16 + (r & 15)) * 512 + q * 16;
    char* ahiB[2] = {sm + ZA_HI0, sm + ZA_HI1};
    char* aloB[2] = {sm + ZA_LO0, sm + ZA_LO1};
    const uint32_t ahiS[2] = {smb + ZA_HI0, smb + ZA_HI1};
    const uint32_t aloS[2] = {smb + ZA_LO0, smb + ZA_LO1};

    unsigned gen0 = 0;
    if (tid == 0) gen0 = g_gen;
    unsigned epoch = 0;
    __syncthreads();

    for (int nt = 0; nt < 128; ++nt) {
        const int t0 = nt * 8;
        const float* xt = xrow_p + (size_t)t0 * 32768;

        float acc[16];
#pragma unroll
        for (int i = 0; i < 16; ++i) acc[i] = 0.f;

        // preload chunk 0
        float4 f0 = *(const float4*)(xt + 0);
        float4 f1 = *(const float4*)(xt + 4);
        float4 f2 = *(const float4*)(xt + 8);
        float4 f3 = *(const float4*)(xt + 12);

        for (int kc = 0; kc < 8; ++kc) {
            // convert + store chunk kc into buffer kc&1
            {
                uint4 hu0, hu1, lu0, lu1;
                hu0.x = pack_hi_lo(f0.x, f0.y, lu0.x);
                hu0.y = pack_hi_lo(f0.z, f0.w, lu0.y);
                hu0.z = pack_hi_lo(f1.x, f1.y, lu0.z);
                hu0.w = pack_hi_lo(f1.z, f1.w, lu0.w);
                hu1.x = pack_hi_lo(f2.x, f2.y, lu1.x);
                hu1.y = pack_hi_lo(f2.z, f2.w, lu1.y);
                hu1.z = pack_hi_lo(f3.x, f3.y, lu1.z);
                hu1.w = pack_hi_lo(f3.z, f3.w, lu1.w);
                char* ah = ahiB[kc & 1] + r * 144 + q * 32;
                char* al = aloB[kc & 1] + r * 144 + q * 32;
                *(uint4*)(ah) = hu0;
                *(uint4*)(ah + 16) = hu1;
                *(uint4*)(al) = lu0;
                *(uint4*)(al + 16) = lu1;
            }
            __syncthreads();

            // issue next chunk's loads (latency hidden under mma)
            if (kc < 7) {
                const float* xn = xt + (kc + 1) * 64;
                f0 = *(const float4*)(xn + 0);
                f1 = *(const float4*)(xn + 4);
                f2 = *(const float4*)(xn + 8);
                f3 = *(const float4*)(xn + 12);
            }

            // mma over this chunk (4 k16 steps x 12 mma: hihi, hilo, lohi)
            const uint32_t ah_s = ahiS[kc & 1];
            const uint32_t al_s = aloS[kc & 1];
            const uint32_t kbyte = (uint32_t)kc * 128;
#pragma unroll
            for (int ks = 0; ks < 4; ++ks) {
                const uint32_t ko = kbyte + ks * 32;
                uint32_t ah0[4], ah1[4], bh[4], bl[4], al0[4], al1[4];
                ldm4(ah0, ah_s + amr + ks * 32);
                ldm4(ah1, ah_s + amr + 2304 + ks * 32);
                ldm4(bh, bhi_lane + ko);
                mma16816(acc + 0,  ah0, bh + 0);
                mma16816(acc + 4,  ah0, bh + 2);
                mma16816(acc + 8,  ah1, bh + 0);
                mma16816(acc + 12, ah1, bh + 2);
                ldm4(bl, blo_lane + ko);
                mma16816(acc + 0,  ah0, bl + 0);
                mma16816(acc + 4,  ah0, bl + 2);
                mma16816(acc + 8,  ah1, bl + 0);
                mma16816(acc + 12, ah1, bl + 2);
                ldm4(al0, al_s + amr + ks * 32);
                ldm4(al1, al_s + amr + 2304 + ks * 32);
                mma16816(acc + 0,  al0, bh + 0);
                mma16816(acc + 4,  al0, bh + 2);
                mma16816(acc + 8,  al1, bh + 0);
                mma16816(acc + 12, al1, bh + 2);
            }
            __syncthreads();
        }

        // epilogue: bias + scatter to g_zx layout [t][cta][eb][dloc][gate]
#pragma unroll
        for (int mi = 0; mi < 2; ++mi) {
#pragma unroll
            for (int ni = 0; ni < 2; ++ni) {
                const float* d = acc + mi * 8 + ni * 4;
                int col = nb + 8 * ni + (L & 3) * 2;
                float bv0 = sbias[col], bv1 = sbias[col + 1];
                int row0 = mr + 16 * mi + (L >> 2);
#pragma unroll
                for (int rr = 0; rr < 2; ++rr) {
                    int row = row0 + rr * 8;
                    float* zp = g_zx + (size_t)(t0 + (row >> 4)) * 131072 +
                                bid * 1024 + (row & 15) * 64;
                    zp[(col & 15) * 4 + (col >> 4)] = d[rr * 2 + 0] + bv0;
                    zp[((col + 1) & 15) * 4 + ((col + 1) >> 4)] =
                        d[rr * 2 + 1] + bv1;
                }
            }
        }

        if ((nt & 31) == 31) {   // bound drift (keep x L2-resident)
            __syncthreads();
            if (tid == 0) {
                unsigned a = atomicAdd(&g_count, 1u);
                if (((a + 1u) & (NCTA - 1u)) == 0u) g_gen = g_gen + 1u;
                ++epoch;
                while ((unsigned)(g_gen - gen0) < epoch) __nanosleep(64);
            }
            __syncthreads();
        }
    }
}

// ========================= PHASE 2: recurrence (R7, unchanged) =============
__device__ __forceinline__ void pf16(float* dst, const float* gsrc) {
    int r  = threadIdx.x >> 5;
    int c0 = threadIdx.x & 31;
    const float* s = gsrc + r * 512;
    float* d = dst + r * BUF_STRIDE;
#pragma unroll
    for (int j = 0; j < 4; ++j) {
        int c = c0 + j * 32;
        cpa16(d + c * 4, s + c * 4);
    }
}

__device__ __forceinline__ void fill_ws(float* Ws, const float* W, int d0) {
    for (int i = threadIdx.x; i < 64 * 512; i += NTHR) {
        int c = i >> 9, k = i & 511;
        int zc = ((c >> 4) << 9) + d0 + (c & 15);
        float w = W[(size_t)k * 2048 + zc];
        int kq = k >> 2;
        int u  = (kq & ~7) | ((kq ^ (c >> 2)) & 7);
        Ws[((c << 7) | u) * 4 + (k & 3)] = w;
    }
}

__device__ __forceinline__ void gemm44(const float* __restrict__ Ws,
                                       const float* __restrict__ buf,
                                       unsigned long long* acc,
                                       int cq, int bq, int chunk) {
    const ulonglong2* wb = (const ulonglong2*)Ws + (4 * cq) * 128;
    const ulonglong2* ap = (const ulonglong2*)buf + bq * 129 + chunk * 16;
    const int kq0 = chunk * 16;
#pragma unroll
    for (int kk = 0; kk < 16; ++kk) {
        int kq = kq0 + kk;
        int u  = (kq & ~7) | ((kq ^ cq) & 7);
        ulonglong2 w0 = wb[u];
        ulonglong2 w1 = wb[128 + u];
        ulonglong2 w2 = wb[256 + u];
        ulonglong2 w3 = wb[384 + u];
#pragma unroll
        for (int bi = 0; bi < 4; ++bi) {
            ulonglong2 a = ap[bi * 516 + kk];
            unsigned long long* ac = acc + bi * 4;
            fma2(ac[0], w0.x, a.x);
            fma2(ac[0], w0.y, a.y);
            fma2(ac[1], w1.x, a.x);
            fma2(ac[1], w1.y, a.y);
            fma2(ac[2], w2.x, a.x);
            fma2(ac[2], w2.y, a.y);
            fma2(ac[3], w3.x, a.x);
            fma2(ac[3], w3.y, a.y);
        }
    }
}

__device__ __forceinline__ void write_partials(float* red,
                                               unsigned long long* acc,
                                               int cq, int bq, int chunk) {
#pragma unroll
    for (int bi = 0; bi < 4; ++bi) {
        float2 s0 = *(float2*)&acc[bi * 4 + 0];
        float2 s1 = *(float2*)&acc[bi * 4 + 1];
        float2 s2 = *(float2*)&acc[bi * 4 + 2];
        float2 s3 = *(float2*)&acc[bi * 4 + 3];
        int row = chunk * 16 + bq + 4 * bi;
        *(float4*)&red[row * RED_STRIDE + 4 * cq] =
            make_float4(s0.x + s0.y, s1.x + s1.y, s2.x + s2.y, s3.x + s3.y);
    }
}

extern "C" __global__ void __launch_bounds__(NTHR, 1)
lstm_rec(const float* __restrict__ c0,
         const float* __restrict__ h0,
         const float* __restrict__ Wh,
         float* __restrict__ out,
         long long out_size) {
    extern __shared__ float smem[];
    float* Ws   = smem;
    float* buf0 = smem + WS_FLOATS;
    float* red  = buf0 + 2 * BUF_FLOATS;
    __shared__ unsigned s_fbase;

    const int tid = threadIdx.x;
    const int bid = blockIdx.x;
    const int gd  = bid & 31, gb = bid >> 5;
    const int d0  = gd * 16;

    const int lane  = tid & 31;
    const int warp  = tid >> 5;
    const int cq    = (lane & 7) | ((warp & 1) << 3);
    const int bq    = lane >> 3;
    const int chunk = warp >> 1;

    const int eb   = tid >> 4;
    const int dloc = tid & 15;

    if (tid == 0) s_fbase = ldflag(&g_flags[bid * 8]);
    fill_ws(Ws, Wh, d0);

    float c_reg = 0.f;
    if (tid < 256) c_reg = c0[(gb * 16 + eb) * 512 + d0 + dloc];
    __syncthreads();
    const unsigned fbase = s_fbase;

    const float* zx_base = g_zx + (size_t)bid * 1024;

    for (int t = 0; t < TS; ++t) {
        float4 zx = make_float4(0.f, 0.f, 0.f, 0.f);
        if (tid < 256)
            zx = *(const float4*)(zx_base + (size_t)t * (NCTA * 1024) + tid * 4);

        if (t > 0 && tid < 32) {
            unsigned tgt = fbase + (unsigned)t;
            const unsigned* fp = &g_flags[(gb * 32 + tid) * 8];
            while ((int)(ldflag(fp) - tgt) < 0) __nanosleep(32);
        }
        __syncthreads();

        const float* hsrc = ((t == 0) ? h0 : g_hbuf[t & 1]) + gb * 8192;
        pf16(buf0, hsrc);
        CPA_COMMIT();
        CPA_WAIT0();
        __syncthreads();

        unsigned long long acc[16];
#pragma unroll
        for (int i = 0; i < 16; ++i) acc[i] = 0ULL;
        gemm44(Ws, buf0, acc, cq, bq, chunk);

        write_partials(red, acc, cq, bq, chunk);
        __syncthreads();

        float hh = 0.f, cc = 0.f;
        if (tid < 256) {
            float zi = zx.x, zf = zx.y, zg = zx.z, zo = zx.w;
#pragma unroll
            for (int ch = 0; ch < 8; ++ch) {
                const float* r = &red[(ch * 16 + eb) * RED_STRIDE + dloc];
                zi += r[0];
                zf += r[16];
                zg += r[32];
                zo += r[48];
            }
            cc = sigf(zf) * c_reg + sigf(zi) * tanhfast(zg);
            hh = sigf(zo) * tanhfast(cc);
            c_reg = cc;
            __stcg(&g_hbuf[(t + 1) & 1][(gb * 16 + eb) * 512 + d0 + dloc], hh);
        }
        __syncthreads();

        if (tid == 0) {
            asm volatile("fence.acq_rel.gpu;" ::: "memory");
            __stcg(&g_flags[bid * 8], fbase + (unsigned)(t + 1));
        }

        if (tid < 256) {
            int d = d0 + dloc;
            int bgl = gb * 16 + eb;
            out[(size_t)t * 32768 + bgl * 512 + d] = hh;
            if (t == TS - 1 && out_size >= 33554432LL + 65536LL) {
                out[33554432 + bgl * 512 + d] = cc;
                out[33554432 + 32768 + bgl * 512 + d] = hh;
            }
        }
    }
}

extern "C" void kernel_launch(void* const* d_in, const int* in_sizes, int n_in,
                              void* d_out, int out_size) {
    const float* x  = (const float*)d_in[0];
    const float* c0 = (const float*)d_in[1];
    const float* h0 = (const float*)d_in[2];
    const float* Wi = (const float*)d_in[3];
    const float* Wh = (const float*)d_in[4];
    const float* b  = (const float*)d_in[5];

    const int rec_smem = (WS_FLOATS + 2 * BUF_FLOATS + RED_FLOATS) * 4;
    cudaFuncSetAttribute(lstm_zx,
                         cudaFuncAttributeMaxDynamicSharedMemorySize, ZX_SMEM);
    cudaFuncSetAttribute(lstm_rec,
                         cudaFuncAttributeMaxDynamicSharedMemorySize, rec_smem);

    lstm_zx<<<NCTA, NTHR, ZX_SMEM>>>(x, Wi, b);
    lstm_rec<<<NCTA, NTHR, rec_smem>>>(c0, h0, Wh, (float*)d_out,
                                       (long long)out_size);
}

// round 10
// speedup vs baseline: 2.5230x; 1.2909x over previous
#include <cuda_runtime.h>
#include <cuda_bf16.h>
#include <cstdint>

// LSTM T=1024, B=64, D=512 — both phases on HMMA (mma.sync m16n8k16 bf16,
// 3-pass hi/lo split).
// lstm_zx : Zx = x@Wi + b (parallel over t), C tile 128x64 per 8 timesteps.
// lstm_rec: z = Zx + h@Wh; gates. M=16(batch) x N=64 x K=512 per step.
//           h is exchanged as bf16 hi/lo planes (producer-converted).

#define TS   1024
#define NCTA 128
#define NTHR 512

// ---- zx smem layout (bytes) ----
#define ZW_HI   0
#define ZW_LO   66560
#define ZA_HI0  133120
#define ZA_LO0  151552
#define ZA_HI1  169984
#define ZA_LO1  188416
#define ZBIAS   206848
#define ZX_SMEM 207104

// ---- rec smem layout (bytes) ----
#define RW_HI   0          // Wh hi: 64 cols x 1040 B
#define RW_LO   66560
#define RA_HI   133120     // h tile hi: 16 rows x 1040 B
#define RA_LO   149760
#define RRED    166400     // 4 x 16 x 68 floats = 17408
#define REC_SMEM 183808

__device__ float g_zx[(size_t)TS * NCTA * 1024];   // [t][cta][eb][dloc][gate]
__device__ __nv_bfloat16 g_hb[2][2][64 * 512];     // [buf][hi/lo][b][d]
__device__ unsigned g_count = 0;
__device__ volatile unsigned g_gen = 0;
__device__ unsigned g_flags[NCTA * 8];

// ===================== helpers =====================
__device__ __forceinline__ float sigf(float x) {
    return __fdividef(1.0f, 1.0f + __expf(-x));
}
__device__ __forceinline__ float tanhfast(float x) {
    float e = __expf(-2.0f * x);
    return __fdividef(1.0f - e, 1.0f + e);
}
__device__ __forceinline__ unsigned ldflag(const unsigned* p) {
    unsigned v;
    asm volatile("ld.global.cg.u32 %0, [%1];" : "=r"(v) : "l"(p));
    return v;
}
__device__ __forceinline__ void cpa16(void* dst, const void* src) {
    unsigned s = (unsigned)__cvta_generic_to_shared(dst);
    asm volatile("cp.async.cg.shared.global [%0], [%1], 16;" :: "r"(s), "l"(src));
}
#define CPA_COMMIT() asm volatile("cp.async.commit_group;" ::: "memory")
#define CPA_WAIT0()  asm volatile("cp.async.wait_group 0;" ::: "memory")

__device__ __forceinline__ void ldm4(uint32_t* r, uint32_t addr) {
    asm volatile("ldmatrix.sync.aligned.m8n8.x4.shared.b16 {%0,%1,%2,%3}, [%4];"
                 : "=r"(r[0]), "=r"(r[1]), "=r"(r[2]), "=r"(r[3]) : "r"(addr));
}
__device__ __forceinline__ void mma16816(float* d, const uint32_t* a,
                                         const uint32_t* b) {
    asm("mma.sync.aligned.m16n8k16.row.col.f32.bf16.bf16.f32 "
        "{%0,%1,%2,%3}, {%4,%5,%6,%7}, {%8,%9}, {%0,%1,%2,%3};"
        : "+f"(d[0]), "+f"(d[1]), "+f"(d[2]), "+f"(d[3])
        : "r"(a[0]), "r"(a[1]), "r"(a[2]), "r"(a[3]), "r"(b[0]), "r"(b[1]));
}
__device__ __forceinline__ uint32_t pack_hi_lo(float a, float b, uint32_t& lo) {
    __nv_bfloat16 ha = __float2bfloat16(a), hb = __float2bfloat16(b);
    float la = a - __bfloat162float(ha);
    float lb = b - __bfloat162float(hb);
    __nv_bfloat162 l2 = __floats2bfloat162_rn(la, lb);
    lo = *(uint32_t*)&l2;
    __nv_bfloat162 h2;
    h2.x = ha; h2.y = hb;
    return *(uint32_t*)&h2;
}
__device__ __forceinline__ void st_b16(__nv_bfloat16* p, __nv_bfloat16 v) {
    unsigned short u = *(unsigned short*)&v;
    asm volatile("st.global.cg.b16 [%0], %1;" :: "l"(p), "h"(u));
}

// convert bf16 hi/lo weight planes: [64 cols x 520 b16], stride 1040 B
__device__ __forceinline__ void fill_w_bf16(char* whi, char* wlo,
                                            const float* W, int d0) {
    for (int i = threadIdx.x; i < 64 * 512; i += NTHR) {
        int c = i >> 9, k = i & 511;
        int zc = ((c >> 4) << 9) + d0 + (c & 15);
        float w = W[(size_t)k * 2048 + zc];
        __nv_bfloat16 h = __float2bfloat16(w);
        __nv_bfloat16 l = __float2bfloat16(w - __bfloat162float(h));
        int off = c * 1040 + k * 2;
        *(__nv_bfloat16*)(whi + off) = h;
        *(__nv_bfloat16*)(wlo + off) = l;
    }
}

// ========================= PHASE 1: HMMA Zx (R9, unchanged) ================
extern "C" __global__ void __launch_bounds__(NTHR, 1)
lstm_zx(const float* __restrict__ x,
        const float* __restrict__ Wi,
        const float* __restrict__ bias) {
    extern __shared__ char sm[];
    const uint32_t smb = (uint32_t)__cvta_generic_to_shared(sm);
    float* sbias = (float*)(sm + ZBIAS);

    const int tid = threadIdx.x;
    const int bid = blockIdx.x;
    const int gd = bid & 31, gb = bid >> 5;
    const int d0 = gd * 16;
    const int wid = tid >> 5;
    const int L   = tid & 31;

    fill_w_bf16(sm + ZW_HI, sm + ZW_LO, Wi, d0);
    if (tid < 64)
        sbias[tid] = bias[(tid >> 4) * 512 + d0 + (tid & 15)];

    const int mr = (wid & 3) * 32;
    const int nb = (wid >> 2) * 16;

    const uint32_t amr = (uint32_t)((mr + (L & 15)) * 144 + (L >> 4) * 16);
    const uint32_t boff =
        (uint32_t)((nb + (L & 7) + ((L >> 4) & 1) * 8) * 1040 +
                   ((L >> 3) & 1) * 16);
    const uint32_t bhi_lane = smb + ZW_HI + boff;
    const uint32_t blo_lane = smb + ZW_LO + boff;

    const int r = tid >> 2;
    const int q = tid & 3;
    const float* xrow_p = x + (size_t)(r >> 4) * 32768 +
                          (size_t)(gb * 16 + (r & 15)) * 512 + q * 16;
    char* ahiB[2] = {sm + ZA_HI0, sm + ZA_HI1};
    char* aloB[2] = {sm + ZA_LO0, sm + ZA_LO1};
    const uint32_t ahiS[2] = {smb + ZA_HI0, smb + ZA_HI1};
    const uint32_t aloS[2] = {smb + ZA_LO0, smb + ZA_LO1};

    unsigned gen0 = 0;
    if (tid == 0) gen0 = g_gen;
    unsigned epoch = 0;
    __syncthreads();

    for (int nt = 0; nt < 128; ++nt) {
        const int t0 = nt * 8;
        const float* xt = xrow_p + (size_t)t0 * 32768;

        float acc[16];
#pragma unroll
        for (int i = 0; i < 16; ++i) acc[i] = 0.f;

        float4 f0 = *(const float4*)(xt + 0);
        float4 f1 = *(const float4*)(xt + 4);
        float4 f2 = *(const float4*)(xt + 8);
        float4 f3 = *(const float4*)(xt + 12);

        for (int kc = 0; kc < 8; ++kc) {
            {
                uint4 hu0, hu1, lu0, lu1;
                hu0.x = pack_hi_lo(f0.x, f0.y, lu0.x);
                hu0.y = pack_hi_lo(f0.z, f0.w, lu0.y);
                hu0.z = pack_hi_lo(f1.x, f1.y, lu0.z);
                hu0.w = pack_hi_lo(f1.z, f1.w, lu0.w);
                hu1.x = pack_hi_lo(f2.x, f2.y, lu1.x);
                hu1.y = pack_hi_lo(f2.z, f2.w, lu1.y);
                hu1.z = pack_hi_lo(f3.x, f3.y, lu1.z);
                hu1.w = pack_hi_lo(f3.z, f3.w, lu1.w);
                char* ah = ahiB[kc & 1] + r * 144 + q * 32;
                char* al = aloB[kc & 1] + r * 144 + q * 32;
                *(uint4*)(ah) = hu0;
                *(uint4*)(ah + 16) = hu1;
                *(uint4*)(al) = lu0;
                *(uint4*)(al + 16) = lu1;
            }
            __syncthreads();

            if (kc < 7) {
                const float* xn = xt + (kc + 1) * 64;
                f0 = *(const float4*)(xn + 0);
                f1 = *(const float4*)(xn + 4);
                f2 = *(const float4*)(xn + 8);
                f3 = *(const float4*)(xn + 12);
            }

            const uint32_t ah_s = ahiS[kc & 1];
            const uint32_t al_s = aloS[kc & 1];
            const uint32_t kbyte = (uint32_t)kc * 128;
#pragma unroll
            for (int ks = 0; ks < 4; ++ks) {
                const uint32_t ko = kbyte + ks * 32;
                uint32_t ah0[4], ah1[4], bh[4], bl[4], al0[4], al1[4];
                ldm4(ah0, ah_s + amr + ks * 32);
                ldm4(ah1, ah_s + amr + 2304 + ks * 32);
                ldm4(bh, bhi_lane + ko);
                mma16816(acc + 0,  ah0, bh + 0);
                mma16816(acc + 4,  ah0, bh + 2);
                mma16816(acc + 8,  ah1, bh + 0);
                mma16816(acc + 12, ah1, bh + 2);
                ldm4(bl, blo_lane + ko);
                mma16816(acc + 0,  ah0, bl + 0);
                mma16816(acc + 4,  ah0, bl + 2);
                mma16816(acc + 8,  ah1, bl + 0);
                mma16816(acc + 12, ah1, bl + 2);
                ldm4(al0, al_s + amr + ks * 32);
                ldm4(al1, al_s + amr + 2304 + ks * 32);
                mma16816(acc + 0,  al0, bh + 0);
                mma16816(acc + 4,  al0, bh + 2);
                mma16816(acc + 8,  al1, bh + 0);
                mma16816(acc + 12, al1, bh + 2);
            }
            __syncthreads();
        }

#pragma unroll
        for (int mi = 0; mi < 2; ++mi) {
#pragma unroll
            for (int ni = 0; ni < 2; ++ni) {
                const float* d = acc + mi * 8 + ni * 4;
                int col = nb + 8 * ni + (L & 3) * 2;
                float bv0 = sbias[col], bv1 = sbias[col + 1];
                int row0 = mr + 16 * mi + (L >> 2);
#pragma unroll
                for (int rr = 0; rr < 2; ++rr) {
                    int row = row0 + rr * 8;
                    float* zp = g_zx + (size_t)(t0 + (row >> 4)) * 131072 +
                                bid * 1024 + (row & 15) * 64;
                    zp[(col & 15) * 4 + (col >> 4)] = d[rr * 2 + 0] + bv0;
                    zp[((col + 1) & 15) * 4 + ((col + 1) >> 4)] =
                        d[rr * 2 + 1] + bv1;
                }
            }
        }

        if ((nt & 31) == 31) {
            __syncthreads();
            if (tid == 0) {
                unsigned a = atomicAdd(&g_count, 1u);
                if (((a + 1u) & (NCTA - 1u)) == 0u) g_gen = g_gen + 1u;
                ++epoch;
                while ((unsigned)(g_gen - gen0) < epoch) __nanosleep(64);
            }
            __syncthreads();
        }
    }
}

// ========================= PHASE 2: HMMA recurrence =========================
extern "C" __global__ void __launch_bounds__(NTHR, 1)
lstm_rec(const float* __restrict__ c0,
         const float* __restrict__ h0,
         const float* __restrict__ Wh,
         float* __restrict__ out,
         long long out_size) {
    extern __shared__ char sm[];
    const uint32_t smb = (uint32_t)__cvta_generic_to_shared(sm);
    float* red = (float*)(sm + RRED);
    __shared__ unsigned s_fbase;

    const int tid = threadIdx.x;
    const int bid = blockIdx.x;
    const int gd  = bid & 31, gb = bid >> 5;
    const int d0  = gd * 16;
    const int wid = tid >> 5;
    const int L   = tid & 31;

    if (tid == 0) s_fbase = ldflag(&g_flags[bid * 8]);
    fill_w_bf16(sm + RW_HI, sm + RW_LO, Wh, d0);

    // warp tiling: nq = n16-tile (cols nq*16..), kq = k-quarter (128 k)
    const int nq = wid & 3;
    const int kq = wid >> 2;

    const uint32_t amr = (uint32_t)((L & 15) * 1040 + (L >> 4) * 16);
    const uint32_t boff =
        (uint32_t)((nq * 16 + (L & 7) + ((L >> 4) & 1) * 8) * 1040 +
                   ((L >> 3) & 1) * 16);
    const uint32_t a_hi = smb + RA_HI + amr + kq * 256;
    const uint32_t a_lo = smb + RA_LO + amr + kq * 256;
    const uint32_t b_hi = smb + RW_HI + boff + kq * 256;
    const uint32_t b_lo = smb + RW_LO + boff + kq * 256;

    // reducer / gate roles
    const int eb   = tid >> 4;   // tid<256: batch 0..15
    const int dloc = tid & 15;

    // h staging roles
    const int hr = tid >> 5;     // row 0..15
    const int hc = tid & 31;     // chunk base

    float c_reg = 0.f;
    if (tid < 256) c_reg = c0[(gb * 16 + eb) * 512 + d0 + dloc];
    __syncthreads();
    const unsigned fbase = s_fbase;

    const float* zx_base = g_zx + (size_t)bid * 1024;

    for (int t = 0; t < TS; ++t) {
        float4 zx = make_float4(0.f, 0.f, 0.f, 0.f);
        if (tid < 256)
            zx = *(const float4*)(zx_base + (size_t)t * (NCTA * 1024) + tid * 4);

        if (t > 0 && tid < 32) {
            unsigned tgt = fbase + (unsigned)t;
            const unsigned* fp = &g_flags[(gb * 32 + tid) * 8];
            while ((int)(ldflag(fp) - tgt) < 0) __nanosleep(32);
        }
        __syncthreads();

        // ---- stage h (bf16 hi/lo) into smem ----
        if (t == 0) {
            // convert h0 fp32 -> bf16 hi/lo (one-time)
            const float* hp = h0 + (size_t)(gb * 16 + hr) * 512 + hc * 16;
            float4 f0 = *(const float4*)(hp + 0);
            float4 f1 = *(const float4*)(hp + 4);
            float4 f2 = *(const float4*)(hp + 8);
            float4 f3 = *(const float4*)(hp + 12);
            uint4 hu0, hu1, lu0, lu1;
            hu0.x = pack_hi_lo(f0.x, f0.y, lu0.x);
            hu0.y = pack_hi_lo(f0.z, f0.w, lu0.y);
            hu0.z = pack_hi_lo(f1.x, f1.y, lu0.z);
            hu0.w = pack_hi_lo(f1.z, f1.w, lu0.w);
            hu1.x = pack_hi_lo(f2.x, f2.y, lu1.x);
            hu1.y = pack_hi_lo(f2.z, f2.w, lu1.y);
            hu1.z = pack_hi_lo(f3.x, f3.y, lu1.z);
            hu1.w = pack_hi_lo(f3.z, f3.w, lu1.w);
            char* ah = sm + RA_HI + hr * 1040 + hc * 32;
            char* al = sm + RA_LO + hr * 1040 + hc * 32;
            *(uint4*)(ah) = hu0;
            *(uint4*)(ah + 16) = hu1;
            *(uint4*)(al) = lu0;
            *(uint4*)(al + 16) = lu1;
        } else {
            const __nv_bfloat16* hhi = g_hb[t & 1][0] + (size_t)(gb * 16 + hr) * 512;
            const __nv_bfloat16* hlo = g_hb[t & 1][1] + (size_t)(gb * 16 + hr) * 512;
            char* ah = sm + RA_HI + hr * 1040;
            char* al = sm + RA_LO + hr * 1040;
            cpa16(ah + hc * 16,        (const char*)hhi + hc * 16);
            cpa16(ah + (hc + 32) * 16, (const char*)hhi + (hc + 32) * 16);
            cpa16(al + hc * 16,        (const char*)hlo + hc * 16);
            cpa16(al + (hc + 32) * 16, (const char*)hlo + (hc + 32) * 16);
            CPA_COMMIT();
            CPA_WAIT0();
        }
        __syncthreads();

        // ---- mma: 8 k16 steps x (2 n8) x 3 passes ----
        float acc[8];
#pragma unroll
        for (int i = 0; i < 8; ++i) acc[i] = 0.f;
#pragma unroll
        for (int ks = 0; ks < 8; ++ks) {
            const uint32_t ko = (uint32_t)ks * 32;
            uint32_t ah[4], al[4], bh[4], bl[4];
            ldm4(ah, a_hi + ko);
            ldm4(bh, b_hi + ko);
            mma16816(acc + 0, ah, bh + 0);
            mma16816(acc + 4, ah, bh + 2);
            ldm4(bl, b_lo + ko);
            mma16816(acc + 0, ah, bl + 0);
            mma16816(acc + 4, ah, bl + 2);
            ldm4(al, a_lo + ko);
            mma16816(acc + 0, al, bh + 0);
            mma16816(acc + 4, al, bh + 2);
        }

        // ---- partials: red[kq][16 rows][68] ----
        {
            int c0i = nq * 16 + (L & 3) * 2;
            int row0 = L >> 2;
#pragma unroll
            for (int rr = 0; rr < 2; ++rr) {
                int row = row0 + rr * 8;
                float* rp = &red[(kq * 16 + row) * 68];
                *(float2*)(rp + c0i)     = make_float2(acc[rr * 2 + 0],
                                                       acc[rr * 2 + 1]);
                *(float2*)(rp + c0i + 8) = make_float2(acc[4 + rr * 2 + 0],
                                                       acc[4 + rr * 2 + 1]);
            }
        }
        __syncthreads();

        // ---- reduce + gates + state update ----
        float hh = 0.f, cc = 0.f;
        if (tid < 256) {
            float zi = zx.x, zf = zx.y, zg = zx.z, zo = zx.w;
#pragma unroll
            for (int k4 = 0; k4 < 4; ++k4) {
                const float* r = &red[(k4 * 16 + eb) * 68 + dloc];
                zi += r[0];
                zf += r[16];
                zg += r[32];
                zo += r[48];
            }
            cc = sigf(zf) * c_reg + sigf(zi) * tanhfast(zg);
            hh = sigf(zo) * tanhfast(cc);
            c_reg = cc;
            // store h as bf16 hi/lo planes (producer-side conversion)
            __nv_bfloat16 hhi = __float2bfloat16(hh);
            __nv_bfloat16 hlo = __float2bfloat16(hh - __bfloat162float(hhi));
            size_t hoff = (size_t)(gb * 16 + eb) * 512 + d0 + dloc;
            st_b16(&g_hb[(t + 1) & 1][0][hoff], hhi);
            st_b16(&g_hb[(t + 1) & 1][1][hoff], hlo);
        }
        __syncthreads();

        if (tid == 0) {
            asm volatile("fence.acq_rel.gpu;" ::: "memory");
            __stcg(&g_flags[bid * 8], fbase + (unsigned)(t + 1));
        }

        // ys / final-state writes off the inter-CTA critical path
        if (tid < 256) {
            int d = d0 + dloc;
            int bgl = gb * 16 + eb;
            out[(size_t)t * 32768 + bgl * 512 + d] = hh;
            if (t == TS - 1 && out_size >= 33554432LL + 65536LL) {
                out[33554432 + bgl * 512 + d] = cc;
                out[33554432 + 32768 + bgl * 512 + d] = hh;
            }
        }
    }
}

extern "C" void kernel_launch(void* const* d_in, const int* in_sizes, int n_in,
                              void* d_out, int out_size) {
    const float* x  = (const float*)d_in[0];
    const float* c0 = (const float*)d_in[1];
    const float* h0 = (const float*)d_in[2];
    const float* Wi = (const float*)d_in[3];
    const float* Wh = (const float*)d_in[4];
    const float* b  = (const float*)d_in[5];

    cudaFuncSetAttribute(lstm_zx,
                         cudaFuncAttributeMaxDynamicSharedMemorySize, ZX_SMEM);
    cudaFuncSetAttribute(lstm_rec,
                         cudaFuncAttributeMaxDynamicSharedMemorySize, REC_SMEM);

    lstm_zx<<<NCTA, NTHR, ZX_SMEM>>>(x, Wi, b);
    lstm_rec<<<NCTA, NTHR, REC_SMEM>>>(c0, h0, Wh, (float*)d_out,
                                       (long long)out_size);
}